// round 1
// baseline (speedup 1.0000x reference)
#include <cuda_runtime.h>
#include <math.h>
#include <stdint.h>

#define N_VERTS 100000
#define N_FACES 200000
#define DIM 512

// ---------------- scratch (no allocations allowed) ----------------
__device__ float g_buf0[(size_t)N_FACES * DIM];   // face_feat, then h2
__device__ float g_buf1[(size_t)N_FACES * DIM];   // h1
__device__ float g_h3[(size_t)N_FACES * 256];     // h3
__device__ float g_out12[(size_t)N_FACES * 12];   // final 12-dim head
__device__ float g_sum[N_VERTS * 3];
__device__ float g_cnt[N_VERTS];

// ---------------- zero accumulators (graph-replay safe) ----------------
__global__ void zero_kernel() {
    int i = blockIdx.x * blockDim.x + threadIdx.x;
    if (i < N_VERTS * 3) g_sum[i] = 0.0f;
    if (i < N_VERTS) g_cnt[i] = 0.0f;
}

// ---------------- gather + mean over 3 face verts ----------------
__global__ void gather_mean_kernel(const float* __restrict__ features,
                                   const int* __restrict__ faces,
                                   float* __restrict__ out) {
    int f = blockIdx.x;
    int c = threadIdx.x;           // 128 threads, one float4 each (512 floats)
    int i0 = faces[f * 3 + 0];
    int i1 = faces[f * 3 + 1];
    int i2 = faces[f * 3 + 2];
    const float4* r0 = (const float4*)(features + (size_t)i0 * DIM);
    const float4* r1 = (const float4*)(features + (size_t)i1 * DIM);
    const float4* r2 = (const float4*)(features + (size_t)i2 * DIM);
    float4 a = r0[c], b = r1[c], d = r2[c];
    const float k = 1.0f / 3.0f;
    float4 r;
    r.x = (a.x + b.x + d.x) * k;
    r.y = (a.y + b.y + d.y) * k;
    r.z = (a.z + b.z + d.z) * k;
    r.w = (a.w + b.w + d.w) * k;
    ((float4*)(out + (size_t)f * DIM))[c] = r;
}

// ---------------- tiled SGEMM: C = act(A[M,K] @ B[K,N] + bias) ----------------
// BM=BN=128, BK=16, 256 threads, 8x8 per thread. N % 128 == 0, K % 16 == 0.
__global__ __launch_bounds__(256, 2)
void sgemm_bias_act(const float* __restrict__ A, const float* __restrict__ B,
                    const float* __restrict__ bias, float* __restrict__ C,
                    int M, int N, int K, int doRelu) {
    const int BM = 128, BN = 128, BK = 16;
    __shared__ float As[BK][BM];
    __shared__ float Bs[BK][BN];

    const int tid = threadIdx.x;
    const int bm = blockIdx.y * BM;
    const int bn = blockIdx.x * BN;
    const int tx = tid & 15;       // 16 thread cols
    const int ty = tid >> 4;       // 16 thread rows

    float acc[8][8];
#pragma unroll
    for (int i = 0; i < 8; i++)
#pragma unroll
        for (int j = 0; j < 8; j++) acc[i][j] = 0.0f;

    for (int k0 = 0; k0 < K; k0 += BK) {
        // A tile: 128 rows x 16 cols = 512 float4; store transposed into As[k][m]
#pragma unroll
        for (int it = 0; it < 2; it++) {
            int idx = tid + it * 256;
            int row = idx >> 2;
            int col = (idx & 3) * 4;
            float4 v = make_float4(0.f, 0.f, 0.f, 0.f);
            int gr = bm + row;
            if (gr < M) v = *(const float4*)&A[(size_t)gr * K + k0 + col];
            As[col + 0][row] = v.x;
            As[col + 1][row] = v.y;
            As[col + 2][row] = v.z;
            As[col + 3][row] = v.w;
        }
        // B tile: 16 rows x 128 cols = 512 float4
#pragma unroll
        for (int it = 0; it < 2; it++) {
            int idx = tid + it * 256;
            int row = idx >> 5;
            int col = (idx & 31) * 4;
            float4 v = *(const float4*)&B[(size_t)(k0 + row) * N + bn + col];
            *(float4*)&Bs[row][col] = v;
        }
        __syncthreads();

#pragma unroll
        for (int k = 0; k < BK; k++) {
            float a[8], b[8];
#pragma unroll
            for (int i = 0; i < 8; i++) a[i] = As[k][ty * 8 + i];
#pragma unroll
            for (int j = 0; j < 8; j++) b[j] = Bs[k][tx * 8 + j];
#pragma unroll
            for (int i = 0; i < 8; i++)
#pragma unroll
                for (int j = 0; j < 8; j++) acc[i][j] += a[i] * b[j];
        }
        __syncthreads();
    }

#pragma unroll
    for (int i = 0; i < 8; i++) {
        int gr = bm + ty * 8 + i;
        if (gr >= M) continue;
#pragma unroll
        for (int j = 0; j < 8; j += 4) {
            int gc = bn + tx * 8 + j;
            float4 v;
            v.x = acc[i][j + 0] + bias[gc + 0];
            v.y = acc[i][j + 1] + bias[gc + 1];
            v.z = acc[i][j + 2] + bias[gc + 2];
            v.w = acc[i][j + 3] + bias[gc + 3];
            if (doRelu) {
                v.x = fmaxf(v.x, 0.f); v.y = fmaxf(v.y, 0.f);
                v.z = fmaxf(v.z, 0.f); v.w = fmaxf(v.w, 0.f);
            }
            *(float4*)&C[(size_t)gr * N + gc] = v;
        }
    }
}

// ---------------- final tiny GEMM: out12 = h3[ M,256 ] @ W4[256,12] + b4 ----------------
__global__ void gemm4_kernel(const float* __restrict__ A, const float* __restrict__ W4,
                             const float* __restrict__ b4, float* __restrict__ out12) {
    __shared__ float Ws[12][256];
    __shared__ float bs[12];
    int tid = threadIdx.x;  // 128
    for (int i = tid; i < 256 * 12; i += 128) {
        int k = i / 12, j = i % 12;
        Ws[j][k] = W4[i];
    }
    if (tid < 12) bs[tid] = b4[tid];
    __syncthreads();

    int warp = tid >> 5, lane = tid & 31;
    int row = blockIdx.x * 4 + warp;
    if (row >= N_FACES) return;
    const float* a = A + (size_t)row * 256;
    float acc[12];
#pragma unroll
    for (int j = 0; j < 12; j++) acc[j] = 0.0f;
    for (int k = lane; k < 256; k += 32) {
        float h = a[k];
#pragma unroll
        for (int j = 0; j < 12; j++) acc[j] += h * Ws[j][k];
    }
#pragma unroll
    for (int j = 0; j < 12; j++) {
#pragma unroll
        for (int off = 16; off; off >>= 1)
            acc[j] += __shfl_down_sync(0xffffffffu, acc[j], off);
    }
    if (lane == 0) {
#pragma unroll
        for (int j = 0; j < 12; j++) out12[(size_t)row * 12 + j] = acc[j] + bs[j];
    }
}

// ---------------- 3x3 SVD-based procrustes + transform + scatter ----------------
__device__ __forceinline__ void jrot(double A[3][3], double V[3][3], int p, int q) {
    double apq = A[p][q];
    if (fabs(apq) < 1e-300) return;
    double tau = (A[q][q] - A[p][p]) / (2.0 * apq);
    double t = copysign(1.0, tau) / (fabs(tau) + sqrt(1.0 + tau * tau));
    double c = 1.0 / sqrt(1.0 + t * t);
    double s = t * c;
#pragma unroll
    for (int k = 0; k < 3; k++) {
        double akp = A[k][p], akq = A[k][q];
        A[k][p] = c * akp - s * akq;
        A[k][q] = s * akp + c * akq;
    }
#pragma unroll
    for (int k = 0; k < 3; k++) {
        double apk = A[p][k], aqk = A[q][k];
        A[p][k] = c * apk - s * aqk;
        A[q][k] = s * apk + c * aqk;
    }
#pragma unroll
    for (int k = 0; k < 3; k++) {
        double vkp = V[k][p], vkq = V[k][q];
        V[k][p] = c * vkp - s * vkq;
        V[k][q] = s * vkp + c * vkq;
    }
}

__global__ void procrustes_kernel(const float* __restrict__ out12,
                                  const float* __restrict__ verts,
                                  const int* __restrict__ faces,
                                  float* __restrict__ out_trans,
                                  float* __restrict__ out_rot) {
    int f = blockIdx.x * blockDim.x + threadIdx.x;
    if (f >= N_FACES) return;

    double Mm[3][3];
#pragma unroll
    for (int i = 0; i < 3; i++)
#pragma unroll
        for (int j = 0; j < 3; j++)
            Mm[i][j] = (double)out12[(size_t)f * 12 + i * 3 + j];

    // A = M^T M
    double A[3][3], V[3][3];
#pragma unroll
    for (int i = 0; i < 3; i++)
#pragma unroll
        for (int j = 0; j < 3; j++) {
            double s = 0.0;
#pragma unroll
            for (int k = 0; k < 3; k++) s += Mm[k][i] * Mm[k][j];
            A[i][j] = s;
            V[i][j] = (i == j) ? 1.0 : 0.0;
        }

    // cyclic Jacobi (8 sweeps is overkill for 3x3)
#pragma unroll
    for (int sweep = 0; sweep < 8; sweep++) {
        jrot(A, V, 0, 1);
        jrot(A, V, 0, 2);
        jrot(A, V, 1, 2);
    }

    // sort eigenvalues descending, swap V columns accordingly
    double lam[3] = {A[0][0], A[1][1], A[2][2]};
#pragma unroll
    for (int a = 0; a < 2; a++) {
        int mx = a;
#pragma unroll
        for (int b = 0; b < 3; b++)
            if (b > a && lam[b] > lam[mx]) mx = b;
        if (mx != a) {
            double tl = lam[a]; lam[a] = lam[mx]; lam[mx] = tl;
#pragma unroll
            for (int k = 0; k < 3; k++) {
                double tv = V[k][a]; V[k][a] = V[k][mx]; V[k][mx] = tv;
            }
        }
    }

    // B = M V  (columns = sigma_i * u_i)
    double Bc[3][3];
#pragma unroll
    for (int i = 0; i < 3; i++)
#pragma unroll
        for (int k = 0; k < 3; k++) {
            double s = 0.0;
#pragma unroll
            for (int j = 0; j < 3; j++) s += Mm[i][j] * V[j][k];
            Bc[i][k] = s;
        }

    double u1[3], u2[3], u3[3];
    double n1 = sqrt(Bc[0][0] * Bc[0][0] + Bc[1][0] * Bc[1][0] + Bc[2][0] * Bc[2][0]);
    double in1 = 1.0 / fmax(n1, 1e-150);
#pragma unroll
    for (int i = 0; i < 3; i++) u1[i] = Bc[i][0] * in1;
    double d12 = u1[0] * Bc[0][1] + u1[1] * Bc[1][1] + u1[2] * Bc[2][1];
    double w[3];
#pragma unroll
    for (int i = 0; i < 3; i++) w[i] = Bc[i][1] - d12 * u1[i];
    double n2 = sqrt(w[0] * w[0] + w[1] * w[1] + w[2] * w[2]);
    double in2 = 1.0 / fmax(n2, 1e-150);
#pragma unroll
    for (int i = 0; i < 3; i++) u2[i] = w[i] * in2;
    u3[0] = u1[1] * u2[2] - u1[2] * u2[1];
    u3[1] = u1[2] * u2[0] - u1[0] * u2[2];
    u3[2] = u1[0] * u2[1] - u1[1] * u2[0];

    double detV = V[0][0] * (V[1][1] * V[2][2] - V[1][2] * V[2][1])
                - V[0][1] * (V[1][0] * V[2][2] - V[1][2] * V[2][0])
                + V[0][2] * (V[1][0] * V[2][1] - V[1][1] * V[2][0]);

    // R = u1 v1^T + u2 v2^T + detV * u3 v3^T   (== U diag(1,1,det(UV^T)) V^T)
    float R[3][3];
#pragma unroll
    for (int i = 0; i < 3; i++)
#pragma unroll
        for (int j = 0; j < 3; j++)
            R[i][j] = (float)(u1[i] * V[j][0] + u2[i] * V[j][1] + detV * u3[i] * V[j][2]);

#pragma unroll
    for (int i = 0; i < 3; i++)
#pragma unroll
        for (int j = 0; j < 3; j++)
            out_rot[(size_t)f * 9 + i * 3 + j] = R[i][j];

    float t0 = out12[(size_t)f * 12 + 9];
    float t1 = out12[(size_t)f * 12 + 10];
    float t2 = out12[(size_t)f * 12 + 11];

#pragma unroll
    for (int c = 0; c < 3; c++) {
        int vi = faces[f * 3 + c];
        float vx = verts[(size_t)vi * 3 + 0];
        float vy = verts[(size_t)vi * 3 + 1];
        float vz = verts[(size_t)vi * 3 + 2];
        float tvx = vx * R[0][0] + vy * R[1][0] + vz * R[2][0] + t0;
        float tvy = vx * R[0][1] + vy * R[1][1] + vz * R[2][1] + t1;
        float tvz = vx * R[0][2] + vy * R[1][2] + vz * R[2][2] + t2;
        out_trans[(size_t)f * 9 + c * 3 + 0] = tvx;
        out_trans[(size_t)f * 9 + c * 3 + 1] = tvy;
        out_trans[(size_t)f * 9 + c * 3 + 2] = tvz;
        atomicAdd(&g_sum[vi * 3 + 0], tvx);
        atomicAdd(&g_sum[vi * 3 + 1], tvy);
        atomicAdd(&g_sum[vi * 3 + 2], tvz);
        atomicAdd(&g_cnt[vi], 1.0f);
    }
}

// ---------------- finalize segment mean ----------------
__global__ void finalize_kernel(float* __restrict__ out_vfeat) {
    int v = blockIdx.x * blockDim.x + threadIdx.x;
    if (v >= N_VERTS) return;
    float c = fmaxf(g_cnt[v], 1.0f);
    float inv = 1.0f / c;
    out_vfeat[v * 3 + 0] = g_sum[v * 3 + 0] * inv;
    out_vfeat[v * 3 + 1] = g_sum[v * 3 + 1] * inv;
    out_vfeat[v * 3 + 2] = g_sum[v * 3 + 2] * inv;
}

// ---------------- launch ----------------
extern "C" void kernel_launch(void* const* d_in, const int* in_sizes, int n_in,
                              void* d_out, int out_size) {
    const float* verts    = (const float*)d_in[0];
    const float* features = (const float*)d_in[1];
    const int*   faces    = (const int*)d_in[2];
    const float* W1 = (const float*)d_in[3];
    const float* b1 = (const float*)d_in[4];
    const float* W2 = (const float*)d_in[5];
    const float* b2 = (const float*)d_in[6];
    const float* W3 = (const float*)d_in[7];
    const float* b3 = (const float*)d_in[8];
    const float* W4 = (const float*)d_in[9];
    const float* b4 = (const float*)d_in[10];

    float* out = (float*)d_out;
    float* out_vfeat = out;                       // [1,100000,3]
    float* out_trans = out + (size_t)N_VERTS * 3; // [200000,3,3]
    float* out_rot   = out_trans + (size_t)N_FACES * 9;

    float *p_buf0, *p_buf1, *p_h3, *p_out12;
    cudaGetSymbolAddress((void**)&p_buf0, g_buf0);
    cudaGetSymbolAddress((void**)&p_buf1, g_buf1);
    cudaGetSymbolAddress((void**)&p_h3, g_h3);
    cudaGetSymbolAddress((void**)&p_out12, g_out12);

    // 1. zero accumulators
    zero_kernel<<<(N_VERTS * 3 + 255) / 256, 256>>>();

    // 2. gather + mean
    gather_mean_kernel<<<N_FACES, 128>>>(features, faces, p_buf0);

    // 3. MLP
    {
        dim3 blk(256);
        dim3 g1(DIM / 128, (N_FACES + 127) / 128);
        sgemm_bias_act<<<g1, blk>>>(p_buf0, W1, b1, p_buf1, N_FACES, DIM, DIM, 1);
        sgemm_bias_act<<<g1, blk>>>(p_buf1, W2, b2, p_buf0, N_FACES, DIM, DIM, 1);
        dim3 g3(256 / 128, (N_FACES + 127) / 128);
        sgemm_bias_act<<<g3, blk>>>(p_buf0, W3, b3, p_h3, N_FACES, 256, DIM, 1);
        gemm4_kernel<<<(N_FACES + 3) / 4, 128>>>(p_h3, W4, b4, p_out12);
    }

    // 4. procrustes + transform + scatter
    procrustes_kernel<<<(N_FACES + 255) / 256, 256>>>(p_out12, verts, faces,
                                                      out_trans, out_rot);

    // 5. segment mean
    finalize_kernel<<<(N_VERTS + 255) / 256, 256>>>(out_vfeat);
}

// round 3
// speedup vs baseline: 2.8131x; 2.8131x over previous
#include <cuda_runtime.h>
#include <cuda_bf16.h>
#include <math.h>
#include <stdint.h>

#define N_VERTS 100000
#define N_FACES 200000
#define DIM 512

// ===================== portable PTX helpers (sm_80+) =====================
__device__ __forceinline__ uint32_t smem_to_u32(const void* smem_ptr) {
    uint32_t addr;
    asm("{ .reg .u64 tmp; cvta.to.shared.u64 tmp, %1; cvt.u32.u64 %0, tmp; }"
        : "=r"(addr) : "l"(smem_ptr));
    return addr;
}

__device__ __forceinline__ void cp16(uint32_t dst, const void* src) {
    asm volatile("cp.async.cg.shared.global [%0], [%1], 16;"
                 :: "r"(dst), "l"(src) : "memory");
}

__device__ __forceinline__ void ldm_x4(uint32_t (&r)[4], uint32_t addr) {
    asm volatile("ldmatrix.sync.aligned.m8n8.x4.shared.b16 {%0,%1,%2,%3}, [%4];"
                 : "=r"(r[0]), "=r"(r[1]), "=r"(r[2]), "=r"(r[3]) : "r"(addr));
}

__device__ __forceinline__ void mma_bf16(float (&d)[4], const uint32_t (&a)[4],
                                         uint32_t b0, uint32_t b1) {
    asm volatile(
        "mma.sync.aligned.m16n8k16.row.col.f32.bf16.bf16.f32 "
        "{%0,%1,%2,%3}, {%4,%5,%6,%7}, {%8,%9}, {%0,%1,%2,%3};"
        : "+f"(d[0]), "+f"(d[1]), "+f"(d[2]), "+f"(d[3])
        : "r"(a[0]), "r"(a[1]), "r"(a[2]), "r"(a[3]), "r"(b0), "r"(b1));
}

__device__ __forceinline__ uint32_t pack_bf16(float a, float b) {
    __nv_bfloat162 t = __floats2bfloat162_rn(a, b);
    return *(uint32_t*)&t;
}

// ===================== scratch (no allocations allowed) =====================
__device__ __nv_bfloat16 g_x_hi[(size_t)N_FACES * DIM];
__device__ __nv_bfloat16 g_x_lo[(size_t)N_FACES * DIM];
__device__ __nv_bfloat16 g_y_hi[(size_t)N_FACES * DIM];
__device__ __nv_bfloat16 g_y_lo[(size_t)N_FACES * DIM];
__device__ float g_h3[(size_t)N_FACES * 256];
__device__ float g_out12[(size_t)N_FACES * 12];
__device__ float g_sum[N_VERTS * 3];
__device__ float g_cnt[N_VERTS];
// transposed + split weights: Wt[n][k] = W[k][n]
__device__ __nv_bfloat16 g_w1t_hi[DIM * DIM];
__device__ __nv_bfloat16 g_w1t_lo[DIM * DIM];
__device__ __nv_bfloat16 g_w2t_hi[DIM * DIM];
__device__ __nv_bfloat16 g_w2t_lo[DIM * DIM];
__device__ __nv_bfloat16 g_w3t_hi[256 * DIM];
__device__ __nv_bfloat16 g_w3t_lo[256 * DIM];

// ===================== zero accumulators =====================
__global__ void zero_kernel() {
    int i = blockIdx.x * blockDim.x + threadIdx.x;
    if (i < N_VERTS * 3) g_sum[i] = 0.0f;
    if (i < N_VERTS) g_cnt[i] = 0.0f;
}

// ===================== weight transpose + split =====================
__global__ void convert_w_kernel(const float* __restrict__ W,
                                 __nv_bfloat16* __restrict__ Thi,
                                 __nv_bfloat16* __restrict__ Tlo,
                                 int K, int N) {
    int id = blockIdx.x * blockDim.x + threadIdx.x;
    if (id >= K * N) return;
    int k = id / N, n = id % N;
    float v = W[id];
    __nv_bfloat16 h = __float2bfloat16(v);
    float lo = v - __bfloat162float(h);
    Thi[(size_t)n * K + k] = h;
    Tlo[(size_t)n * K + k] = __float2bfloat16(lo);
}

// ===================== gather + mean, emit bf16 hi/lo =====================
__global__ void gather_mean_kernel(const float* __restrict__ features,
                                   const int* __restrict__ faces,
                                   __nv_bfloat16* __restrict__ outHi,
                                   __nv_bfloat16* __restrict__ outLo) {
    int f = blockIdx.x;
    int c = threadIdx.x;  // 128 threads x float4
    int i0 = faces[f * 3 + 0];
    int i1 = faces[f * 3 + 1];
    int i2 = faces[f * 3 + 2];
    const float4* r0 = (const float4*)(features + (size_t)i0 * DIM);
    const float4* r1 = (const float4*)(features + (size_t)i1 * DIM);
    const float4* r2 = (const float4*)(features + (size_t)i2 * DIM);
    float4 a = r0[c], b = r1[c], d = r2[c];
    const float k = 1.0f / 3.0f;
    float v[4];
    v[0] = (a.x + b.x + d.x) * k;
    v[1] = (a.y + b.y + d.y) * k;
    v[2] = (a.z + b.z + d.z) * k;
    v[3] = (a.w + b.w + d.w) * k;
    uint32_t ph[2], pl[2];
#pragma unroll
    for (int p = 0; p < 2; p++) {
        float hv0, hv1;
        __nv_bfloat16 h0 = __float2bfloat16(v[2 * p]);
        __nv_bfloat16 h1 = __float2bfloat16(v[2 * p + 1]);
        hv0 = __bfloat162float(h0);
        hv1 = __bfloat162float(h1);
        ph[p] = (uint32_t)__bfloat16_as_ushort(h0) |
                ((uint32_t)__bfloat16_as_ushort(h1) << 16);
        pl[p] = pack_bf16(v[2 * p] - hv0, v[2 * p + 1] - hv1);
    }
    *(uint2*)(outHi + (size_t)f * DIM + c * 4) = make_uint2(ph[0], ph[1]);
    *(uint2*)(outLo + (size_t)f * DIM + c * 4) = make_uint2(pl[0], pl[1]);
}

// ===================== HMMA split-bf16 GEMM =====================
// D[M, N_TOTAL] = relu(A @ Wt^T + bias). A hi/lo bf16 [M,512]; Wt hi/lo [N_TOTAL,512].
// CTA tile 128x128, BK=32, double-buffered cp.async.
// SMEM stage: Ahi/Alo/Bhi/Blo each [128][40] bf16 (80B row stride, 16B pad).
// OUT_MODE 0: write bf16 hi/lo. OUT_MODE 1: write f32.
#define STG_BYTES   40960           // 4 * 128 * 80
#define BUF_BYTES   10240           // 128 * 80
#define ROW_B       80              // bytes per smem row
#define SM_TOTAL_G  (2 * STG_BYTES) // 81920

template <int N_TOTAL, int OUT_MODE>
__global__ void __launch_bounds__(256, 1)
gemm_hmma(const __nv_bfloat16* __restrict__ Ahi,
          const __nv_bfloat16* __restrict__ Alo,
          const __nv_bfloat16* __restrict__ Bhi,
          const __nv_bfloat16* __restrict__ Blo,
          const float* __restrict__ bias,
          void* __restrict__ outHiV, void* __restrict__ outLoV,
          int M) {
    extern __shared__ char smem[];
    const uint32_t su = smem_to_u32(smem);
    const int tid = threadIdx.x;
    const int m0 = blockIdx.y * 128;
    const int n0 = blockIdx.x * 128;

    const int lane = tid & 31;
    const int warp = tid >> 5;
    const int wm = warp & 3;   // 4 warps along M (32 rows each)
    const int wn = warp >> 2;  // 2 warps along N (64 cols each)

    // ldmatrix lane address bases
    const uint32_t aRow = wm * 32 + (lane & 15);
    const uint32_t aCol = (lane >> 4) * 16;           // +16B for k+8
    const uint32_t bRow = wn * 64 + (lane & 7) + ((lane & 16) >> 1);
    const uint32_t bCol = (lane & 8) ? 16u : 0u;

    const uint32_t aHiB = su + aRow * ROW_B + aCol;               // buf0
    const uint32_t aLoB = aHiB + BUF_BYTES;                       // buf1
    const uint32_t bHiB = su + 2 * BUF_BYTES + bRow * ROW_B + bCol; // buf2
    const uint32_t bLoB = bHiB + BUF_BYTES;                       // buf3

    // cp.async mapping: i in 0..7 -> buf=i>>1, row=(i&1)*64 + tid/4, q=tid&3
    const int ldRowHalf = tid >> 2;
    const int ldQ = tid & 3;

    float acc[2][8][4];
#pragma unroll
    for (int t = 0; t < 2; t++)
#pragma unroll
        for (int j = 0; j < 8; j++)
#pragma unroll
            for (int e = 0; e < 4; e++) acc[t][j][e] = 0.0f;

    // -------- stage loader --------
    auto load_stage = [&](uint32_t stageBase, int kc) {
        const int k0 = kc * 32;
#pragma unroll
        for (int i = 0; i < 8; i++) {
            const int buf = i >> 1;
            const int r = (i & 1) * 64 + ldRowHalf;
            const uint32_t dst = su + stageBase + buf * BUF_BYTES +
                                 r * ROW_B + ldQ * 16;
            const __nv_bfloat16* srcp;
            if (buf == 0) {
                int gr = m0 + r; if (gr >= M) gr = M - 1;
                srcp = Ahi + (size_t)gr * DIM + k0 + ldQ * 8;
            } else if (buf == 1) {
                int gr = m0 + r; if (gr >= M) gr = M - 1;
                srcp = Alo + (size_t)gr * DIM + k0 + ldQ * 8;
            } else if (buf == 2) {
                srcp = Bhi + (size_t)(n0 + r) * DIM + k0 + ldQ * 8;
            } else {
                srcp = Blo + (size_t)(n0 + r) * DIM + k0 + ldQ * 8;
            }
            cp16(dst, srcp);
        }
        asm volatile("cp.async.commit_group;" ::: "memory");
    };

    // prologue: chunks 0 and 1
    load_stage(0, 0);
    load_stage(STG_BYTES, 1);

    for (int kc = 0; kc < 16; kc++) {
        if (kc == 15) {
            asm volatile("cp.async.wait_group 0;" ::: "memory");
        } else {
            asm volatile("cp.async.wait_group 1;" ::: "memory");
        }
        __syncthreads();

        const uint32_t sb = (uint32_t)(kc & 1) * STG_BYTES;
#pragma unroll
        for (int h = 0; h < 2; h++) {
            const uint32_t hoff = sb + h * 32;
            uint32_t ah[2][4], al[2][4];
            ldm_x4(ah[0], aHiB + hoff);
            ldm_x4(ah[1], aHiB + hoff + 16 * ROW_B);
            ldm_x4(al[0], aLoB + hoff);
            ldm_x4(al[1], aLoB + hoff + 16 * ROW_B);
#pragma unroll
            for (int p = 0; p < 4; p++) {
                uint32_t bh[4], bl[4];
                ldm_x4(bh, bHiB + hoff + p * (16 * ROW_B));
                ldm_x4(bl, bLoB + hoff + p * (16 * ROW_B));
#pragma unroll
                for (int t = 0; t < 2; t++) {
                    mma_bf16(acc[t][2 * p],     ah[t], bh[0], bh[1]);
                    mma_bf16(acc[t][2 * p],     ah[t], bl[0], bl[1]);
                    mma_bf16(acc[t][2 * p],     al[t], bh[0], bh[1]);
                    mma_bf16(acc[t][2 * p + 1], ah[t], bh[2], bh[3]);
                    mma_bf16(acc[t][2 * p + 1], ah[t], bl[2], bl[3]);
                    mma_bf16(acc[t][2 * p + 1], al[t], bh[2], bh[3]);
                }
            }
        }
        __syncthreads();
        if (kc + 2 < 16) load_stage(sb, kc + 2);
    }

    // -------- epilogue: stage accumulators in smem as f32 [128][132] --------
    float* sout = (float*)smem;
#pragma unroll
    for (int t = 0; t < 2; t++)
#pragma unroll
        for (int j = 0; j < 8; j++) {
            const int row = wm * 32 + t * 16 + (lane >> 2);
            const int col = wn * 64 + j * 8 + (lane & 3) * 2;
            sout[row * 132 + col]           = acc[t][j][0];
            sout[row * 132 + col + 1]       = acc[t][j][1];
            sout[(row + 8) * 132 + col]     = acc[t][j][2];
            sout[(row + 8) * 132 + col + 1] = acc[t][j][3];
        }
    __syncthreads();

#pragma unroll
    for (int i = 0; i < 16; i++) {
        const int lin = tid + i * 256;   // 0..4095
        const int row = lin >> 5;
        const int q = lin & 31;
        const int gr = m0 + row;
        if (gr >= M) continue;
        float4 v = *(float4*)&sout[row * 132 + q * 4];
        const float4 bb = __ldg((const float4*)&bias[n0 + q * 4]);
        v.x = fmaxf(v.x + bb.x, 0.0f);
        v.y = fmaxf(v.y + bb.y, 0.0f);
        v.z = fmaxf(v.z + bb.z, 0.0f);
        v.w = fmaxf(v.w + bb.w, 0.0f);
        if (OUT_MODE == 0) {
            __nv_bfloat16 h0 = __float2bfloat16(v.x);
            __nv_bfloat16 h1 = __float2bfloat16(v.y);
            __nv_bfloat16 h2 = __float2bfloat16(v.z);
            __nv_bfloat16 h3 = __float2bfloat16(v.w);
            uint2 vh, vl;
            vh.x = (uint32_t)__bfloat16_as_ushort(h0) |
                   ((uint32_t)__bfloat16_as_ushort(h1) << 16);
            vh.y = (uint32_t)__bfloat16_as_ushort(h2) |
                   ((uint32_t)__bfloat16_as_ushort(h3) << 16);
            vl.x = pack_bf16(v.x - __bfloat162float(h0),
                             v.y - __bfloat162float(h1));
            vl.y = pack_bf16(v.z - __bfloat162float(h2),
                             v.w - __bfloat162float(h3));
            const size_t off = (size_t)gr * N_TOTAL + n0 + q * 4;
            *(uint2*)((__nv_bfloat16*)outHiV + off) = vh;
            *(uint2*)((__nv_bfloat16*)outLoV + off) = vl;
        } else {
            *(float4*)((float*)outHiV + (size_t)gr * N_TOTAL + n0 + q * 4) = v;
        }
    }
}

// ===================== final tiny GEMM =====================
__global__ void gemm4_kernel(const float* __restrict__ A, const float* __restrict__ W4,
                             const float* __restrict__ b4, float* __restrict__ out12) {
    __shared__ float Ws[12][256];
    __shared__ float bs[12];
    int tid = threadIdx.x;  // 128
    for (int i = tid; i < 256 * 12; i += 128) {
        int k = i / 12, j = i % 12;
        Ws[j][k] = W4[i];
    }
    if (tid < 12) bs[tid] = b4[tid];
    __syncthreads();

    int warp = tid >> 5, lane = tid & 31;
    int row = blockIdx.x * 4 + warp;
    if (row >= N_FACES) return;
    const float* a = A + (size_t)row * 256;
    float acc[12];
#pragma unroll
    for (int j = 0; j < 12; j++) acc[j] = 0.0f;
    for (int k = lane; k < 256; k += 32) {
        float h = a[k];
#pragma unroll
        for (int j = 0; j < 12; j++) acc[j] += h * Ws[j][k];
    }
#pragma unroll
    for (int j = 0; j < 12; j++) {
#pragma unroll
        for (int off = 16; off; off >>= 1)
            acc[j] += __shfl_down_sync(0xffffffffu, acc[j], off);
    }
    if (lane == 0) {
#pragma unroll
        for (int j = 0; j < 12; j++) out12[(size_t)row * 12 + j] = acc[j] + bs[j];
    }
}

// ===================== procrustes + transform + scatter =====================
__device__ __forceinline__ void jrot(double A[3][3], double V[3][3], int p, int q) {
    double apq = A[p][q];
    if (fabs(apq) < 1e-300) return;
    double tau = (A[q][q] - A[p][p]) / (2.0 * apq);
    double t = copysign(1.0, tau) / (fabs(tau) + sqrt(1.0 + tau * tau));
    double c = 1.0 / sqrt(1.0 + t * t);
    double s = t * c;
#pragma unroll
    for (int k = 0; k < 3; k++) {
        double akp = A[k][p], akq = A[k][q];
        A[k][p] = c * akp - s * akq;
        A[k][q] = s * akp + c * akq;
    }
#pragma unroll
    for (int k = 0; k < 3; k++) {
        double apk = A[p][k], aqk = A[q][k];
        A[p][k] = c * apk - s * aqk;
        A[q][k] = s * apk + c * aqk;
    }
#pragma unroll
    for (int k = 0; k < 3; k++) {
        double vkp = V[k][p], vkq = V[k][q];
        V[k][p] = c * vkp - s * vkq;
        V[k][q] = s * vkp + c * vkq;
    }
}

__global__ void procrustes_kernel(const float* __restrict__ out12,
                                  const float* __restrict__ verts,
                                  const int* __restrict__ faces,
                                  float* __restrict__ out_trans,
                                  float* __restrict__ out_rot) {
    int f = blockIdx.x * blockDim.x + threadIdx.x;
    if (f >= N_FACES) return;

    double Mm[3][3];
#pragma unroll
    for (int i = 0; i < 3; i++)
#pragma unroll
        for (int j = 0; j < 3; j++)
            Mm[i][j] = (double)out12[(size_t)f * 12 + i * 3 + j];

    double A[3][3], V[3][3];
#pragma unroll
    for (int i = 0; i < 3; i++)
#pragma unroll
        for (int j = 0; j < 3; j++) {
            double s = 0.0;
#pragma unroll
            for (int k = 0; k < 3; k++) s += Mm[k][i] * Mm[k][j];
            A[i][j] = s;
            V[i][j] = (i == j) ? 1.0 : 0.0;
        }

#pragma unroll
    for (int sweep = 0; sweep < 8; sweep++) {
        jrot(A, V, 0, 1);
        jrot(A, V, 0, 2);
        jrot(A, V, 1, 2);
    }

    double lam[3] = {A[0][0], A[1][1], A[2][2]};
#pragma unroll
    for (int a = 0; a < 2; a++) {
        int mx = a;
#pragma unroll
        for (int b = 0; b < 3; b++)
            if (b > a && lam[b] > lam[mx]) mx = b;
        if (mx != a) {
            double tl = lam[a]; lam[a] = lam[mx]; lam[mx] = tl;
#pragma unroll
            for (int k = 0; k < 3; k++) {
                double tv = V[k][a]; V[k][a] = V[k][mx]; V[k][mx] = tv;
            }
        }
    }

    double Bc[3][3];
#pragma unroll
    for (int i = 0; i < 3; i++)
#pragma unroll
        for (int k = 0; k < 3; k++) {
            double s = 0.0;
#pragma unroll
            for (int j = 0; j < 3; j++) s += Mm[i][j] * V[j][k];
            Bc[i][k] = s;
        }

    double u1[3], u2[3], u3[3];
    double n1 = sqrt(Bc[0][0] * Bc[0][0] + Bc[1][0] * Bc[1][0] + Bc[2][0] * Bc[2][0]);
    double in1 = 1.0 / fmax(n1, 1e-150);
#pragma unroll
    for (int i = 0; i < 3; i++) u1[i] = Bc[i][0] * in1;
    double d12 = u1[0] * Bc[0][1] + u1[1] * Bc[1][1] + u1[2] * Bc[2][1];
    double w[3];
#pragma unroll
    for (int i = 0; i < 3; i++) w[i] = Bc[i][1] - d12 * u1[i];
    double n2 = sqrt(w[0] * w[0] + w[1] * w[1] + w[2] * w[2]);
    double in2 = 1.0 / fmax(n2, 1e-150);
#pragma unroll
    for (int i = 0; i < 3; i++) u2[i] = w[i] * in2;
    u3[0] = u1[1] * u2[2] - u1[2] * u2[1];
    u3[1] = u1[2] * u2[0] - u1[0] * u2[2];
    u3[2] = u1[0] * u2[1] - u1[1] * u2[0];

    double detV = V[0][0] * (V[1][1] * V[2][2] - V[1][2] * V[2][1])
                - V[0][1] * (V[1][0] * V[2][2] - V[1][2] * V[2][0])
                + V[0][2] * (V[1][0] * V[2][1] - V[1][1] * V[2][0]);

    float R[3][3];
#pragma unroll
    for (int i = 0; i < 3; i++)
#pragma unroll
        for (int j = 0; j < 3; j++)
            R[i][j] = (float)(u1[i] * V[j][0] + u2[i] * V[j][1] + detV * u3[i] * V[j][2]);

#pragma unroll
    for (int i = 0; i < 3; i++)
#pragma unroll
        for (int j = 0; j < 3; j++)
            out_rot[(size_t)f * 9 + i * 3 + j] = R[i][j];

    float t0 = out12[(size_t)f * 12 + 9];
    float t1 = out12[(size_t)f * 12 + 10];
    float t2 = out12[(size_t)f * 12 + 11];

#pragma unroll
    for (int c = 0; c < 3; c++) {
        int vi = faces[f * 3 + c];
        float vx = verts[(size_t)vi * 3 + 0];
        float vy = verts[(size_t)vi * 3 + 1];
        float vz = verts[(size_t)vi * 3 + 2];
        float tvx = vx * R[0][0] + vy * R[1][0] + vz * R[2][0] + t0;
        float tvy = vx * R[0][1] + vy * R[1][1] + vz * R[2][1] + t1;
        float tvz = vx * R[0][2] + vy * R[1][2] + vz * R[2][2] + t2;
        out_trans[(size_t)f * 9 + c * 3 + 0] = tvx;
        out_trans[(size_t)f * 9 + c * 3 + 1] = tvy;
        out_trans[(size_t)f * 9 + c * 3 + 2] = tvz;
        atomicAdd(&g_sum[vi * 3 + 0], tvx);
        atomicAdd(&g_sum[vi * 3 + 1], tvy);
        atomicAdd(&g_sum[vi * 3 + 2], tvz);
        atomicAdd(&g_cnt[vi], 1.0f);
    }
}

// ===================== finalize segment mean =====================
__global__ void finalize_kernel(float* __restrict__ out_vfeat) {
    int v = blockIdx.x * blockDim.x + threadIdx.x;
    if (v >= N_VERTS) return;
    float c = fmaxf(g_cnt[v], 1.0f);
    float inv = 1.0f / c;
    out_vfeat[v * 3 + 0] = g_sum[v * 3 + 0] * inv;
    out_vfeat[v * 3 + 1] = g_sum[v * 3 + 1] * inv;
    out_vfeat[v * 3 + 2] = g_sum[v * 3 + 2] * inv;
}

// ===================== launch =====================
extern "C" void kernel_launch(void* const* d_in, const int* in_sizes, int n_in,
                              void* d_out, int out_size) {
    const float* verts    = (const float*)d_in[0];
    const float* features = (const float*)d_in[1];
    const int*   faces    = (const int*)d_in[2];
    const float* W1 = (const float*)d_in[3];
    const float* b1 = (const float*)d_in[4];
    const float* W2 = (const float*)d_in[5];
    const float* b2 = (const float*)d_in[6];
    const float* W3 = (const float*)d_in[7];
    const float* b3 = (const float*)d_in[8];
    const float* W4 = (const float*)d_in[9];
    const float* b4 = (const float*)d_in[10];

    float* out = (float*)d_out;
    float* out_vfeat = out;
    float* out_trans = out + (size_t)N_VERTS * 3;
    float* out_rot   = out_trans + (size_t)N_FACES * 9;

    __nv_bfloat16 *p_x_hi, *p_x_lo, *p_y_hi, *p_y_lo;
    __nv_bfloat16 *p_w1h, *p_w1l, *p_w2h, *p_w2l, *p_w3h, *p_w3l;
    float *p_h3, *p_out12;
    cudaGetSymbolAddress((void**)&p_x_hi, g_x_hi);
    cudaGetSymbolAddress((void**)&p_x_lo, g_x_lo);
    cudaGetSymbolAddress((void**)&p_y_hi, g_y_hi);
    cudaGetSymbolAddress((void**)&p_y_lo, g_y_lo);
    cudaGetSymbolAddress((void**)&p_w1h, g_w1t_hi);
    cudaGetSymbolAddress((void**)&p_w1l, g_w1t_lo);
    cudaGetSymbolAddress((void**)&p_w2h, g_w2t_hi);
    cudaGetSymbolAddress((void**)&p_w2l, g_w2t_lo);
    cudaGetSymbolAddress((void**)&p_w3h, g_w3t_hi);
    cudaGetSymbolAddress((void**)&p_w3l, g_w3t_lo);
    cudaGetSymbolAddress((void**)&p_h3, g_h3);
    cudaGetSymbolAddress((void**)&p_out12, g_out12);

    cudaFuncSetAttribute(gemm_hmma<512, 0>,
                         cudaFuncAttributeMaxDynamicSharedMemorySize, SM_TOTAL_G);
    cudaFuncSetAttribute(gemm_hmma<256, 1>,
                         cudaFuncAttributeMaxDynamicSharedMemorySize, SM_TOTAL_G);

    // 1. zero accumulators
    zero_kernel<<<(N_VERTS * 3 + 255) / 256, 256>>>();

    // 2. weight transpose + split
    convert_w_kernel<<<(DIM * DIM + 255) / 256, 256>>>(W1, p_w1h, p_w1l, DIM, DIM);
    convert_w_kernel<<<(DIM * DIM + 255) / 256, 256>>>(W2, p_w2h, p_w2l, DIM, DIM);
    convert_w_kernel<<<(DIM * 256 + 255) / 256, 256>>>(W3, p_w3h, p_w3l, DIM, 256);

    // 3. gather + mean -> bf16 split
    gather_mean_kernel<<<N_FACES, 128>>>(features, faces, p_x_hi, p_x_lo);

    // 4. MLP on HMMA tensor cores
    {
        dim3 blk(256);
        dim3 g12(4, (N_FACES + 127) / 128);
        gemm_hmma<512, 0><<<g12, blk, SM_TOTAL_G>>>(p_x_hi, p_x_lo, p_w1h, p_w1l,
                                                    b1, p_y_hi, p_y_lo, N_FACES);
        gemm_hmma<512, 0><<<g12, blk, SM_TOTAL_G>>>(p_y_hi, p_y_lo, p_w2h, p_w2l,
                                                    b2, p_x_hi, p_x_lo, N_FACES);
        dim3 g3(2, (N_FACES + 127) / 128);
        gemm_hmma<256, 1><<<g3, blk, SM_TOTAL_G>>>(p_x_hi, p_x_lo, p_w3h, p_w3l,
                                                   b3, p_h3, nullptr, N_FACES);
        gemm4_kernel<<<(N_FACES + 3) / 4, 128>>>(p_h3, W4, b4, p_out12);
    }

    // 5. procrustes + transform + scatter
    procrustes_kernel<<<(N_FACES + 255) / 256, 256>>>(p_out12, verts, faces,
                                                      out_trans, out_rot);

    // 6. segment mean
    finalize_kernel<<<(N_VERTS + 255) / 256, 256>>>(out_vfeat);
}

// round 4
// speedup vs baseline: 2.8634x; 1.0179x over previous
#include <cuda_runtime.h>
#include <cuda_bf16.h>
#include <math.h>
#include <stdint.h>

#define N_VERTS 100000
#define N_FACES 200000
#define DIM 512

// ===================== portable PTX helpers (sm_80+) =====================
__device__ __forceinline__ uint32_t smem_to_u32(const void* smem_ptr) {
    uint32_t addr;
    asm("{ .reg .u64 tmp; cvta.to.shared.u64 tmp, %1; cvt.u32.u64 %0, tmp; }"
        : "=r"(addr) : "l"(smem_ptr));
    return addr;
}

__device__ __forceinline__ void cp16(uint32_t dst, const void* src) {
    asm volatile("cp.async.cg.shared.global [%0], [%1], 16;"
                 :: "r"(dst), "l"(src) : "memory");
}

__device__ __forceinline__ void ldm_x4(uint32_t (&r)[4], uint32_t addr) {
    asm volatile("ldmatrix.sync.aligned.m8n8.x4.shared.b16 {%0,%1,%2,%3}, [%4];"
                 : "=r"(r[0]), "=r"(r[1]), "=r"(r[2]), "=r"(r[3]) : "r"(addr));
}

__device__ __forceinline__ void mma_bf16(float (&d)[4], const uint32_t (&a)[4],
                                         uint32_t b0, uint32_t b1) {
    asm volatile(
        "mma.sync.aligned.m16n8k16.row.col.f32.bf16.bf16.f32 "
        "{%0,%1,%2,%3}, {%4,%5,%6,%7}, {%8,%9}, {%0,%1,%2,%3};"
        : "+f"(d[0]), "+f"(d[1]), "+f"(d[2]), "+f"(d[3])
        : "r"(a[0]), "r"(a[1]), "r"(a[2]), "r"(a[3]), "r"(b0), "r"(b1));
}

__device__ __forceinline__ uint32_t pack_bf16(float a, float b) {
    __nv_bfloat162 t = __floats2bfloat162_rn(a, b);
    return *(uint32_t*)&t;
}

// ===================== scratch (no allocations allowed) =====================
__device__ __nv_bfloat16 g_x_hi[(size_t)N_FACES * DIM];
__device__ __nv_bfloat16 g_x_lo[(size_t)N_FACES * DIM];
__device__ __nv_bfloat16 g_y_hi[(size_t)N_FACES * DIM];
__device__ __nv_bfloat16 g_y_lo[(size_t)N_FACES * DIM];
__device__ float g_h3[(size_t)N_FACES * 256];
__device__ float g_out12[(size_t)N_FACES * 12];
__device__ float g_sum[N_VERTS * 3];
__device__ float g_cnt[N_VERTS];
// transposed + split weights: Wt[n][k] = W[k][n]
__device__ __nv_bfloat16 g_w1t_hi[DIM * DIM];
__device__ __nv_bfloat16 g_w1t_lo[DIM * DIM];
__device__ __nv_bfloat16 g_w2t_hi[DIM * DIM];
__device__ __nv_bfloat16 g_w2t_lo[DIM * DIM];
__device__ __nv_bfloat16 g_w3t_hi[256 * DIM];
__device__ __nv_bfloat16 g_w3t_lo[256 * DIM];

// ===================== zero accumulators =====================
__global__ void zero_kernel() {
    int i = blockIdx.x * blockDim.x + threadIdx.x;
    if (i < N_VERTS * 3) g_sum[i] = 0.0f;
    if (i < N_VERTS) g_cnt[i] = 0.0f;
}

// ===================== weight transpose + split =====================
__global__ void convert_w_kernel(const float* __restrict__ W,
                                 __nv_bfloat16* __restrict__ Thi,
                                 __nv_bfloat16* __restrict__ Tlo,
                                 int K, int N) {
    int id = blockIdx.x * blockDim.x + threadIdx.x;
    if (id >= K * N) return;
    int k = id / N, n = id % N;
    float v = W[id];
    __nv_bfloat16 h = __float2bfloat16(v);
    float lo = v - __bfloat162float(h);
    Thi[(size_t)n * K + k] = h;
    Tlo[(size_t)n * K + k] = __float2bfloat16(lo);
}

// ===================== gather + mean, emit bf16 hi/lo =====================
__global__ void gather_mean_kernel(const float* __restrict__ features,
                                   const int* __restrict__ faces,
                                   __nv_bfloat16* __restrict__ outHi,
                                   __nv_bfloat16* __restrict__ outLo) {
    int f = blockIdx.x;
    int c = threadIdx.x;  // 128 threads x float4
    int i0 = faces[f * 3 + 0];
    int i1 = faces[f * 3 + 1];
    int i2 = faces[f * 3 + 2];
    const float4* r0 = (const float4*)(features + (size_t)i0 * DIM);
    const float4* r1 = (const float4*)(features + (size_t)i1 * DIM);
    const float4* r2 = (const float4*)(features + (size_t)i2 * DIM);
    float4 a = r0[c], b = r1[c], d = r2[c];
    const float k = 1.0f / 3.0f;
    float v[4];
    v[0] = (a.x + b.x + d.x) * k;
    v[1] = (a.y + b.y + d.y) * k;
    v[2] = (a.z + b.z + d.z) * k;
    v[3] = (a.w + b.w + d.w) * k;
    uint32_t ph[2], pl[2];
#pragma unroll
    for (int p = 0; p < 2; p++) {
        __nv_bfloat16 h0 = __float2bfloat16(v[2 * p]);
        __nv_bfloat16 h1 = __float2bfloat16(v[2 * p + 1]);
        float hv0 = __bfloat162float(h0);
        float hv1 = __bfloat162float(h1);
        ph[p] = (uint32_t)__bfloat16_as_ushort(h0) |
                ((uint32_t)__bfloat16_as_ushort(h1) << 16);
        pl[p] = pack_bf16(v[2 * p] - hv0, v[2 * p + 1] - hv1);
    }
    *(uint2*)(outHi + (size_t)f * DIM + c * 4) = make_uint2(ph[0], ph[1]);
    *(uint2*)(outLo + (size_t)f * DIM + c * 4) = make_uint2(pl[0], pl[1]);
}

// ===================== HMMA split-bf16 GEMM (3-stage pipeline) =====================
// D[M, N_TOTAL] = relu(A @ Wt^T + bias). A hi/lo bf16 [M,512]; Wt hi/lo [N_TOTAL,512].
// CTA tile 128x128, BK=32, 3-stage cp.async pipeline, 1 barrier per chunk.
// SMEM stage: Ahi/Alo/Bhi/Blo each [128][40] bf16 (80B row stride).
#define STG_BYTES   40960           // 4 * 128 * 80
#define BUF_BYTES   10240           // 128 * 80
#define ROW_B       80              // bytes per smem row
#define N_STAGES    3
#define SM_TOTAL_G  (N_STAGES * STG_BYTES)  // 122880

template <int N_TOTAL, int OUT_MODE>
__global__ void __launch_bounds__(256, 1)
gemm_hmma(const __nv_bfloat16* __restrict__ Ahi,
          const __nv_bfloat16* __restrict__ Alo,
          const __nv_bfloat16* __restrict__ Bhi,
          const __nv_bfloat16* __restrict__ Blo,
          const float* __restrict__ bias,
          void* __restrict__ outHiV, void* __restrict__ outLoV,
          int M) {
    extern __shared__ char smem[];
    const uint32_t su = smem_to_u32(smem);
    const int tid = threadIdx.x;
    const int m0 = blockIdx.y * 128;
    const int n0 = blockIdx.x * 128;

    const int lane = tid & 31;
    const int warp = tid >> 5;
    const int wm = warp & 3;   // 4 warps along M (32 rows each)
    const int wn = warp >> 2;  // 2 warps along N (64 cols each)

    // ldmatrix lane address bases
    const uint32_t aRow = wm * 32 + (lane & 15);
    const uint32_t aCol = (lane >> 4) * 16;           // +16B for k+8
    const uint32_t bRow = wn * 64 + (lane & 7) + ((lane & 16) >> 1);
    const uint32_t bCol = (lane & 8) ? 16u : 0u;

    const uint32_t aHiB = su + aRow * ROW_B + aCol;               // buf0
    const uint32_t aLoB = aHiB + BUF_BYTES;                       // buf1
    const uint32_t bHiB = su + 2 * BUF_BYTES + bRow * ROW_B + bCol; // buf2
    const uint32_t bLoB = bHiB + BUF_BYTES;                       // buf3

    const int ldRowHalf = tid >> 2;
    const int ldQ = tid & 3;

    float acc[2][8][4];
#pragma unroll
    for (int t = 0; t < 2; t++)
#pragma unroll
        for (int j = 0; j < 8; j++)
#pragma unroll
            for (int e = 0; e < 4; e++) acc[t][j][e] = 0.0f;

    // -------- stage loader (8 cp.async x 16B per thread, 1 commit) --------
    auto load_stage = [&](int stage, int kc) {
        const int k0 = kc * 32;
        const uint32_t stageBase = (uint32_t)stage * STG_BYTES;
#pragma unroll
        for (int i = 0; i < 8; i++) {
            const int buf = i >> 1;
            const int r = (i & 1) * 64 + ldRowHalf;
            const uint32_t dst = su + stageBase + buf * BUF_BYTES +
                                 r * ROW_B + ldQ * 16;
            const __nv_bfloat16* srcp;
            if (buf == 0) {
                int gr = m0 + r; if (gr >= M) gr = M - 1;
                srcp = Ahi + (size_t)gr * DIM + k0 + ldQ * 8;
            } else if (buf == 1) {
                int gr = m0 + r; if (gr >= M) gr = M - 1;
                srcp = Alo + (size_t)gr * DIM + k0 + ldQ * 8;
            } else if (buf == 2) {
                srcp = Bhi + (size_t)(n0 + r) * DIM + k0 + ldQ * 8;
            } else {
                srcp = Blo + (size_t)(n0 + r) * DIM + k0 + ldQ * 8;
            }
            cp16(dst, srcp);
        }
        asm volatile("cp.async.commit_group;" ::: "memory");
    };

    // prologue: stages 0,1 in flight
    load_stage(0, 0);
    load_stage(1, 1);

    int stage = 0;
    for (int kc = 0; kc < 16; kc++) {
        if (kc == 15) {
            asm volatile("cp.async.wait_group 0;" ::: "memory");
        } else {
            asm volatile("cp.async.wait_group 1;" ::: "memory");
        }
        __syncthreads();

        // issue next stage's loads BEFORE compute (overlap DRAM with MMAs)
        if (kc + 2 < 16) {
            int ns = stage + 2; if (ns >= N_STAGES) ns -= N_STAGES;
            load_stage(ns, kc + 2);
        }

        const uint32_t sb = (uint32_t)stage * STG_BYTES;
#pragma unroll
        for (int h = 0; h < 2; h++) {
            const uint32_t hoff = sb + h * 32;
            uint32_t ah[2][4], al[2][4];
            ldm_x4(ah[0], aHiB + hoff);
            ldm_x4(ah[1], aHiB + hoff + 16 * ROW_B);
            ldm_x4(al[0], aLoB + hoff);
            ldm_x4(al[1], aLoB + hoff + 16 * ROW_B);
#pragma unroll
            for (int p = 0; p < 4; p++) {
                uint32_t bh[4], bl[4];
                ldm_x4(bh, bHiB + hoff + p * (16 * ROW_B));
                ldm_x4(bl, bLoB + hoff + p * (16 * ROW_B));
#pragma unroll
                for (int t = 0; t < 2; t++) {
                    // interleave across two accumulator quads (dep distance 2)
                    mma_bf16(acc[t][2 * p],     ah[t], bh[0], bh[1]);
                    mma_bf16(acc[t][2 * p + 1], ah[t], bh[2], bh[3]);
                    mma_bf16(acc[t][2 * p],     ah[t], bl[0], bl[1]);
                    mma_bf16(acc[t][2 * p + 1], ah[t], bl[2], bl[3]);
                    mma_bf16(acc[t][2 * p],     al[t], bh[0], bh[1]);
                    mma_bf16(acc[t][2 * p + 1], al[t], bh[2], bh[3]);
                }
            }
        }
        stage++; if (stage >= N_STAGES) stage = 0;
    }
    __syncthreads();   // all compute done before smem reuse in epilogue

    // -------- epilogue: stage accumulators in smem as f32 [128][132] --------
    float* sout = (float*)smem;
#pragma unroll
    for (int t = 0; t < 2; t++)
#pragma unroll
        for (int j = 0; j < 8; j++) {
            const int row = wm * 32 + t * 16 + (lane >> 2);
            const int col = wn * 64 + j * 8 + (lane & 3) * 2;
            sout[row * 132 + col]           = acc[t][j][0];
            sout[row * 132 + col + 1]       = acc[t][j][1];
            sout[(row + 8) * 132 + col]     = acc[t][j][2];
            sout[(row + 8) * 132 + col + 1] = acc[t][j][3];
        }
    __syncthreads();

#pragma unroll
    for (int i = 0; i < 16; i++) {
        const int lin = tid + i * 256;   // 0..4095
        const int row = lin >> 5;
        const int q = lin & 31;
        const int gr = m0 + row;
        if (gr >= M) continue;
        float4 v = *(float4*)&sout[row * 132 + q * 4];
        const float4 bb = __ldg((const float4*)&bias[n0 + q * 4]);
        v.x = fmaxf(v.x + bb.x, 0.0f);
        v.y = fmaxf(v.y + bb.y, 0.0f);
        v.z = fmaxf(v.z + bb.z, 0.0f);
        v.w = fmaxf(v.w + bb.w, 0.0f);
        if (OUT_MODE == 0) {
            __nv_bfloat16 h0 = __float2bfloat16(v.x);
            __nv_bfloat16 h1 = __float2bfloat16(v.y);
            __nv_bfloat16 h2 = __float2bfloat16(v.z);
            __nv_bfloat16 h3 = __float2bfloat16(v.w);
            uint2 vh, vl;
            vh.x = (uint32_t)__bfloat16_as_ushort(h0) |
                   ((uint32_t)__bfloat16_as_ushort(h1) << 16);
            vh.y = (uint32_t)__bfloat16_as_ushort(h2) |
                   ((uint32_t)__bfloat16_as_ushort(h3) << 16);
            vl.x = pack_bf16(v.x - __bfloat162float(h0),
                             v.y - __bfloat162float(h1));
            vl.y = pack_bf16(v.z - __bfloat162float(h2),
                             v.w - __bfloat162float(h3));
            const size_t off = (size_t)gr * N_TOTAL + n0 + q * 4;
            *(uint2*)((__nv_bfloat16*)outHiV + off) = vh;
            *(uint2*)((__nv_bfloat16*)outLoV + off) = vl;
        } else {
            *(float4*)((float*)outHiV + (size_t)gr * N_TOTAL + n0 + q * 4) = v;
        }
    }
}

// ===================== final tiny GEMM =====================
__global__ void gemm4_kernel(const float* __restrict__ A, const float* __restrict__ W4,
                             const float* __restrict__ b4, float* __restrict__ out12) {
    __shared__ float Ws[12][256];
    __shared__ float bs[12];
    int tid = threadIdx.x;  // 128
    for (int i = tid; i < 256 * 12; i += 128) {
        int k = i / 12, j = i % 12;
        Ws[j][k] = W4[i];
    }
    if (tid < 12) bs[tid] = b4[tid];
    __syncthreads();

    int warp = tid >> 5, lane = tid & 31;
    int row = blockIdx.x * 4 + warp;
    if (row >= N_FACES) return;
    const float* a = A + (size_t)row * 256;
    float acc[12];
#pragma unroll
    for (int j = 0; j < 12; j++) acc[j] = 0.0f;
    for (int k = lane; k < 256; k += 32) {
        float h = a[k];
#pragma unroll
        for (int j = 0; j < 12; j++) acc[j] += h * Ws[j][k];
    }
#pragma unroll
    for (int j = 0; j < 12; j++) {
#pragma unroll
        for (int off = 16; off; off >>= 1)
            acc[j] += __shfl_down_sync(0xffffffffu, acc[j], off);
    }
    if (lane == 0) {
#pragma unroll
        for (int j = 0; j < 12; j++) out12[(size_t)row * 12 + j] = acc[j] + bs[j];
    }
}

// ===================== procrustes + transform + scatter =====================
__device__ __forceinline__ void jrot(double A[3][3], double V[3][3], int p, int q) {
    double apq = A[p][q];
    if (fabs(apq) < 1e-300) return;
    double tau = (A[q][q] - A[p][p]) / (2.0 * apq);
    double t = copysign(1.0, tau) / (fabs(tau) + sqrt(1.0 + tau * tau));
    double c = 1.0 / sqrt(1.0 + t * t);
    double s = t * c;
#pragma unroll
    for (int k = 0; k < 3; k++) {
        double akp = A[k][p], akq = A[k][q];
        A[k][p] = c * akp - s * akq;
        A[k][q] = s * akp + c * akq;
    }
#pragma unroll
    for (int k = 0; k < 3; k++) {
        double apk = A[p][k], aqk = A[q][k];
        A[p][k] = c * apk - s * aqk;
        A[q][k] = s * apk + c * aqk;
    }
#pragma unroll
    for (int k = 0; k < 3; k++) {
        double vkp = V[k][p], vkq = V[k][q];
        V[k][p] = c * vkp - s * vkq;
        V[k][q] = s * vkp + c * vkq;
    }
}

__global__ void procrustes_kernel(const float* __restrict__ out12,
                                  const float* __restrict__ verts,
                                  const int* __restrict__ faces,
                                  float* __restrict__ out_trans,
                                  float* __restrict__ out_rot) {
    int f = blockIdx.x * blockDim.x + threadIdx.x;
    if (f >= N_FACES) return;

    double Mm[3][3];
#pragma unroll
    for (int i = 0; i < 3; i++)
#pragma unroll
        for (int j = 0; j < 3; j++)
            Mm[i][j] = (double)out12[(size_t)f * 12 + i * 3 + j];

    double A[3][3], V[3][3];
#pragma unroll
    for (int i = 0; i < 3; i++)
#pragma unroll
        for (int j = 0; j < 3; j++) {
            double s = 0.0;
#pragma unroll
            for (int k = 0; k < 3; k++) s += Mm[k][i] * Mm[k][j];
            A[i][j] = s;
            V[i][j] = (i == j) ? 1.0 : 0.0;
        }

#pragma unroll
    for (int sweep = 0; sweep < 8; sweep++) {
        jrot(A, V, 0, 1);
        jrot(A, V, 0, 2);
        jrot(A, V, 1, 2);
    }

    double lam[3] = {A[0][0], A[1][1], A[2][2]};
#pragma unroll
    for (int a = 0; a < 2; a++) {
        int mx = a;
#pragma unroll
        for (int b = 0; b < 3; b++)
            if (b > a && lam[b] > lam[mx]) mx = b;
        if (mx != a) {
            double tl = lam[a]; lam[a] = lam[mx]; lam[mx] = tl;
#pragma unroll
            for (int k = 0; k < 3; k++) {
                double tv = V[k][a]; V[k][a] = V[k][mx]; V[k][mx] = tv;
            }
        }
    }

    double Bc[3][3];
#pragma unroll
    for (int i = 0; i < 3; i++)
#pragma unroll
        for (int k = 0; k < 3; k++) {
            double s = 0.0;
#pragma unroll
            for (int j = 0; j < 3; j++) s += Mm[i][j] * V[j][k];
            Bc[i][k] = s;
        }

    double u1[3], u2[3], u3[3];
    double n1 = sqrt(Bc[0][0] * Bc[0][0] + Bc[1][0] * Bc[1][0] + Bc[2][0] * Bc[2][0]);
    double in1 = 1.0 / fmax(n1, 1e-150);
#pragma unroll
    for (int i = 0; i < 3; i++) u1[i] = Bc[i][0] * in1;
    double d12 = u1[0] * Bc[0][1] + u1[1] * Bc[1][1] + u1[2] * Bc[2][1];
    double w[3];
#pragma unroll
    for (int i = 0; i < 3; i++) w[i] = Bc[i][1] - d12 * u1[i];
    double n2 = sqrt(w[0] * w[0] + w[1] * w[1] + w[2] * w[2]);
    double in2 = 1.0 / fmax(n2, 1e-150);
#pragma unroll
    for (int i = 0; i < 3; i++) u2[i] = w[i] * in2;
    u3[0] = u1[1] * u2[2] - u1[2] * u2[1];
    u3[1] = u1[2] * u2[0] - u1[0] * u2[2];
    u3[2] = u1[0] * u2[1] - u1[1] * u2[0];

    double detV = V[0][0] * (V[1][1] * V[2][2] - V[1][2] * V[2][1])
                - V[0][1] * (V[1][0] * V[2][2] - V[1][2] * V[2][0])
                + V[0][2] * (V[1][0] * V[2][1] - V[1][1] * V[2][0]);

    float R[3][3];
#pragma unroll
    for (int i = 0; i < 3; i++)
#pragma unroll
        for (int j = 0; j < 3; j++)
            R[i][j] = (float)(u1[i] * V[j][0] + u2[i] * V[j][1] + detV * u3[i] * V[j][2]);

#pragma unroll
    for (int i = 0; i < 3; i++)
#pragma unroll
        for (int j = 0; j < 3; j++)
            out_rot[(size_t)f * 9 + i * 3 + j] = R[i][j];

    float t0 = out12[(size_t)f * 12 + 9];
    float t1 = out12[(size_t)f * 12 + 10];
    float t2 = out12[(size_t)f * 12 + 11];

#pragma unroll
    for (int c = 0; c < 3; c++) {
        int vi = faces[f * 3 + c];
        float vx = verts[(size_t)vi * 3 + 0];
        float vy = verts[(size_t)vi * 3 + 1];
        float vz = verts[(size_t)vi * 3 + 2];
        float tvx = vx * R[0][0] + vy * R[1][0] + vz * R[2][0] + t0;
        float tvy = vx * R[0][1] + vy * R[1][1] + vz * R[2][1] + t1;
        float tvz = vx * R[0][2] + vy * R[1][2] + vz * R[2][2] + t2;
        out_trans[(size_t)f * 9 + c * 3 + 0] = tvx;
        out_trans[(size_t)f * 9 + c * 3 + 1] = tvy;
        out_trans[(size_t)f * 9 + c * 3 + 2] = tvz;
        atomicAdd(&g_sum[vi * 3 + 0], tvx);
        atomicAdd(&g_sum[vi * 3 + 1], tvy);
        atomicAdd(&g_sum[vi * 3 + 2], tvz);
        atomicAdd(&g_cnt[vi], 1.0f);
    }
}

// ===================== finalize segment mean =====================
__global__ void finalize_kernel(float* __restrict__ out_vfeat) {
    int v = blockIdx.x * blockDim.x + threadIdx.x;
    if (v >= N_VERTS) return;
    float c = fmaxf(g_cnt[v], 1.0f);
    float inv = 1.0f / c;
    out_vfeat[v * 3 + 0] = g_sum[v * 3 + 0] * inv;
    out_vfeat[v * 3 + 1] = g_sum[v * 3 + 1] * inv;
    out_vfeat[v * 3 + 2] = g_sum[v * 3 + 2] * inv;
}

// ===================== launch =====================
extern "C" void kernel_launch(void* const* d_in, const int* in_sizes, int n_in,
                              void* d_out, int out_size) {
    const float* verts    = (const float*)d_in[0];
    const float* features = (const float*)d_in[1];
    const int*   faces    = (const int*)d_in[2];
    const float* W1 = (const float*)d_in[3];
    const float* b1 = (const float*)d_in[4];
    const float* W2 = (const float*)d_in[5];
    const float* b2 = (const float*)d_in[6];
    const float* W3 = (const float*)d_in[7];
    const float* b3 = (const float*)d_in[8];
    const float* W4 = (const float*)d_in[9];
    const float* b4 = (const float*)d_in[10];

    float* out = (float*)d_out;
    float* out_vfeat = out;
    float* out_trans = out + (size_t)N_VERTS * 3;
    float* out_rot   = out_trans + (size_t)N_FACES * 9;

    __nv_bfloat16 *p_x_hi, *p_x_lo, *p_y_hi, *p_y_lo;
    __nv_bfloat16 *p_w1h, *p_w1l, *p_w2h, *p_w2l, *p_w3h, *p_w3l;
    float *p_h3, *p_out12;
    cudaGetSymbolAddress((void**)&p_x_hi, g_x_hi);
    cudaGetSymbolAddress((void**)&p_x_lo, g_x_lo);
    cudaGetSymbolAddress((void**)&p_y_hi, g_y_hi);
    cudaGetSymbolAddress((void**)&p_y_lo, g_y_lo);
    cudaGetSymbolAddress((void**)&p_w1h, g_w1t_hi);
    cudaGetSymbolAddress((void**)&p_w1l, g_w1t_lo);
    cudaGetSymbolAddress((void**)&p_w2h, g_w2t_hi);
    cudaGetSymbolAddress((void**)&p_w2l, g_w2t_lo);
    cudaGetSymbolAddress((void**)&p_w3h, g_w3t_hi);
    cudaGetSymbolAddress((void**)&p_w3l, g_w3t_lo);
    cudaGetSymbolAddress((void**)&p_h3, g_h3);
    cudaGetSymbolAddress((void**)&p_out12, g_out12);

    cudaFuncSetAttribute(gemm_hmma<512, 0>,
                         cudaFuncAttributeMaxDynamicSharedMemorySize, SM_TOTAL_G);
    cudaFuncSetAttribute(gemm_hmma<256, 1>,
                         cudaFuncAttributeMaxDynamicSharedMemorySize, SM_TOTAL_G);

    // 1. zero accumulators
    zero_kernel<<<(N_VERTS * 3 + 255) / 256, 256>>>();

    // 2. weight transpose + split
    convert_w_kernel<<<(DIM * DIM + 255) / 256, 256>>>(W1, p_w1h, p_w1l, DIM, DIM);
    convert_w_kernel<<<(DIM * DIM + 255) / 256, 256>>>(W2, p_w2h, p_w2l, DIM, DIM);
    convert_w_kernel<<<(DIM * 256 + 255) / 256, 256>>>(W3, p_w3h, p_w3l, DIM, 256);

    // 3. gather + mean -> bf16 split
    gather_mean_kernel<<<N_FACES, 128>>>(features, faces, p_x_hi, p_x_lo);

    // 4. MLP on HMMA tensor cores
    {
        dim3 blk(256);
        dim3 g12(4, (N_FACES + 127) / 128);
        gemm_hmma<512, 0><<<g12, blk, SM_TOTAL_G>>>(p_x_hi, p_x_lo, p_w1h, p_w1l,
                                                    b1, p_y_hi, p_y_lo, N_FACES);
        gemm_hmma<512, 0><<<g12, blk, SM_TOTAL_G>>>(p_y_hi, p_y_lo, p_w2h, p_w2l,
                                                    b2, p_x_hi, p_x_lo, N_FACES);
        dim3 g3(2, (N_FACES + 127) / 128);
        gemm_hmma<256, 1><<<g3, blk, SM_TOTAL_G>>>(p_x_hi, p_x_lo, p_w3h, p_w3l,
                                                   b3, p_h3, nullptr, N_FACES);
        gemm4_kernel<<<(N_FACES + 3) / 4, 128>>>(p_h3, W4, b4, p_out12);
    }

    // 5. procrustes + transform + scatter
    procrustes_kernel<<<(N_FACES + 255) / 256, 256>>>(p_out12, verts, faces,
                                                      out_trans, out_rot);

    // 6. segment mean
    finalize_kernel<<<(N_VERTS + 255) / 256, 256>>>(out_vfeat);
}

// round 5
// speedup vs baseline: 3.2473x; 1.1340x over previous
#include <cuda_runtime.h>
#include <cuda_bf16.h>
#include <math.h>
#include <stdint.h>

#define N_VERTS 100000
#define N_FACES 200000
#define DIM 512

// ===================== portable PTX helpers (sm_80+) =====================
__device__ __forceinline__ uint32_t smem_to_u32(const void* smem_ptr) {
    uint32_t addr;
    asm("{ .reg .u64 tmp; cvta.to.shared.u64 tmp, %1; cvt.u32.u64 %0, tmp; }"
        : "=r"(addr) : "l"(smem_ptr));
    return addr;
}

__device__ __forceinline__ void cp16(uint32_t dst, const void* src) {
    asm volatile("cp.async.cg.shared.global [%0], [%1], 16;"
                 :: "r"(dst), "l"(src) : "memory");
}

__device__ __forceinline__ void ldm_x4(uint32_t (&r)[4], uint32_t addr) {
    asm volatile("ldmatrix.sync.aligned.m8n8.x4.shared.b16 {%0,%1,%2,%3}, [%4];"
                 : "=r"(r[0]), "=r"(r[1]), "=r"(r[2]), "=r"(r[3]) : "r"(addr));
}

__device__ __forceinline__ void mma_bf16(float (&d)[4], const uint32_t (&a)[4],
                                         uint32_t b0, uint32_t b1) {
    asm volatile(
        "mma.sync.aligned.m16n8k16.row.col.f32.bf16.bf16.f32 "
        "{%0,%1,%2,%3}, {%4,%5,%6,%7}, {%8,%9}, {%0,%1,%2,%3};"
        : "+f"(d[0]), "+f"(d[1]), "+f"(d[2]), "+f"(d[3])
        : "r"(a[0]), "r"(a[1]), "r"(a[2]), "r"(a[3]), "r"(b0), "r"(b1));
}

__device__ __forceinline__ uint32_t pack_bf16(float a, float b) {
    __nv_bfloat162 t = __floats2bfloat162_rn(a, b);
    return *(uint32_t*)&t;
}

// ===================== scratch (no allocations allowed) =====================
__device__ __nv_bfloat16 g_x_hi[(size_t)N_FACES * DIM];
__device__ __nv_bfloat16 g_x_lo[(size_t)N_FACES * DIM];
__device__ __nv_bfloat16 g_y_hi[(size_t)N_FACES * DIM];
__device__ __nv_bfloat16 g_y_lo[(size_t)N_FACES * DIM];
__device__ float g_h3[(size_t)N_FACES * 256];
__device__ float g_out12[(size_t)N_FACES * 12];
__device__ float g_sum[N_VERTS * 3];
__device__ float g_cnt[N_VERTS];
// transposed + split weights: Wt[n][k] = W[k][n]
__device__ __nv_bfloat16 g_w1t_hi[DIM * DIM];
__device__ __nv_bfloat16 g_w1t_lo[DIM * DIM];
__device__ __nv_bfloat16 g_w2t_hi[DIM * DIM];
__device__ __nv_bfloat16 g_w2t_lo[DIM * DIM];
__device__ __nv_bfloat16 g_w3t_hi[256 * DIM];
__device__ __nv_bfloat16 g_w3t_lo[256 * DIM];

// ===================== zero accumulators =====================
__global__ void zero_kernel() {
    int i = blockIdx.x * blockDim.x + threadIdx.x;
    if (i < N_VERTS * 3) g_sum[i] = 0.0f;
    if (i < N_VERTS) g_cnt[i] = 0.0f;
}

// ===================== weight transpose + split =====================
__global__ void convert_w_kernel(const float* __restrict__ W,
                                 __nv_bfloat16* __restrict__ Thi,
                                 __nv_bfloat16* __restrict__ Tlo,
                                 int K, int N) {
    int id = blockIdx.x * blockDim.x + threadIdx.x;
    if (id >= K * N) return;
    int k = id / N, n = id % N;
    float v = W[id];
    __nv_bfloat16 h = __float2bfloat16(v);
    float lo = v - __bfloat162float(h);
    Thi[(size_t)n * K + k] = h;
    Tlo[(size_t)n * K + k] = __float2bfloat16(lo);
}

// ===================== gather + mean, emit bf16 hi/lo =====================
__global__ void gather_mean_kernel(const float* __restrict__ features,
                                   const int* __restrict__ faces,
                                   __nv_bfloat16* __restrict__ outHi,
                                   __nv_bfloat16* __restrict__ outLo) {
    int f = blockIdx.x;
    int c = threadIdx.x;  // 128 threads x float4
    int i0 = faces[f * 3 + 0];
    int i1 = faces[f * 3 + 1];
    int i2 = faces[f * 3 + 2];
    const float4* r0 = (const float4*)(features + (size_t)i0 * DIM);
    const float4* r1 = (const float4*)(features + (size_t)i1 * DIM);
    const float4* r2 = (const float4*)(features + (size_t)i2 * DIM);
    float4 a = r0[c], b = r1[c], d = r2[c];
    const float k = 1.0f / 3.0f;
    float v[4];
    v[0] = (a.x + b.x + d.x) * k;
    v[1] = (a.y + b.y + d.y) * k;
    v[2] = (a.z + b.z + d.z) * k;
    v[3] = (a.w + b.w + d.w) * k;
    uint32_t ph[2], pl[2];
#pragma unroll
    for (int p = 0; p < 2; p++) {
        __nv_bfloat16 h0 = __float2bfloat16(v[2 * p]);
        __nv_bfloat16 h1 = __float2bfloat16(v[2 * p + 1]);
        float hv0 = __bfloat162float(h0);
        float hv1 = __bfloat162float(h1);
        ph[p] = (uint32_t)__bfloat16_as_ushort(h0) |
                ((uint32_t)__bfloat16_as_ushort(h1) << 16);
        pl[p] = pack_bf16(v[2 * p] - hv0, v[2 * p + 1] - hv1);
    }
    *(uint2*)(outHi + (size_t)f * DIM + c * 4) = make_uint2(ph[0], ph[1]);
    *(uint2*)(outLo + (size_t)f * DIM + c * 4) = make_uint2(pl[0], pl[1]);
}

// ===================== HMMA split-bf16 GEMM (2-stage, 2 CTAs/SM) =====================
// D[M, N_TOTAL] = relu(A @ Wt^T + bias). A hi/lo bf16 [M,512]; Wt hi/lo [N_TOTAL,512].
// CTA tile 128x128, BK=32, 2-stage cp.async pipeline; occupancy 2 -> 16 warps/SM.
#define STG_BYTES   40960           // 4 * 128 * 80
#define BUF_BYTES   10240           // 128 * 80
#define ROW_B       80              // bytes per smem row
#define SM_TOTAL_G  (2 * STG_BYTES) // 81920 (2 CTAs fit in 227KB)

template <int N_TOTAL, int OUT_MODE>
__global__ void __launch_bounds__(256, 2)
gemm_hmma(const __nv_bfloat16* __restrict__ Ahi,
          const __nv_bfloat16* __restrict__ Alo,
          const __nv_bfloat16* __restrict__ Bhi,
          const __nv_bfloat16* __restrict__ Blo,
          const float* __restrict__ bias,
          void* __restrict__ outHiV, void* __restrict__ outLoV,
          int M) {
    extern __shared__ char smem[];
    const uint32_t su = smem_to_u32(smem);
    const int tid = threadIdx.x;
    const int m0 = blockIdx.y * 128;
    const int n0 = blockIdx.x * 128;

    const int lane = tid & 31;
    const int warp = tid >> 5;
    const int wm = warp & 3;   // 4 warps along M (32 rows each)
    const int wn = warp >> 2;  // 2 warps along N (64 cols each)

    // ldmatrix lane address bases
    const uint32_t aRow = wm * 32 + (lane & 15);
    const uint32_t aCol = (lane >> 4) * 16;           // +16B for k+8
    const uint32_t bRow = wn * 64 + (lane & 7) + ((lane & 16) >> 1);
    const uint32_t bCol = (lane & 8) ? 16u : 0u;

    const uint32_t aHiB = su + aRow * ROW_B + aCol;               // buf0
    const uint32_t aLoB = aHiB + BUF_BYTES;                       // buf1
    const uint32_t bHiB = su + 2 * BUF_BYTES + bRow * ROW_B + bCol; // buf2
    const uint32_t bLoB = bHiB + BUF_BYTES;                       // buf3

    const int ldRowHalf = tid >> 2;
    const int ldQ = tid & 3;

    float acc[2][8][4];
#pragma unroll
    for (int t = 0; t < 2; t++)
#pragma unroll
        for (int j = 0; j < 8; j++)
#pragma unroll
            for (int e = 0; e < 4; e++) acc[t][j][e] = 0.0f;

    // -------- stage loader (8 cp.async x 16B per thread, 1 commit) --------
    auto load_stage = [&](int stage, int kc) {
        const int k0 = kc * 32;
        const uint32_t stageBase = (uint32_t)stage * STG_BYTES;
#pragma unroll
        for (int i = 0; i < 8; i++) {
            const int buf = i >> 1;
            const int r = (i & 1) * 64 + ldRowHalf;
            const uint32_t dst = su + stageBase + buf * BUF_BYTES +
                                 r * ROW_B + ldQ * 16;
            const __nv_bfloat16* srcp;
            if (buf == 0) {
                int gr = m0 + r; if (gr >= M) gr = M - 1;
                srcp = Ahi + (size_t)gr * DIM + k0 + ldQ * 8;
            } else if (buf == 1) {
                int gr = m0 + r; if (gr >= M) gr = M - 1;
                srcp = Alo + (size_t)gr * DIM + k0 + ldQ * 8;
            } else if (buf == 2) {
                srcp = Bhi + (size_t)(n0 + r) * DIM + k0 + ldQ * 8;
            } else {
                srcp = Blo + (size_t)(n0 + r) * DIM + k0 + ldQ * 8;
            }
            cp16(dst, srcp);
        }
        asm volatile("cp.async.commit_group;" ::: "memory");
    };

    // prologue: both stages in flight
    load_stage(0, 0);
    load_stage(1, 1);

    for (int kc = 0; kc < 16; kc++) {
        if (kc == 15) {
            asm volatile("cp.async.wait_group 0;" ::: "memory");
        } else {
            asm volatile("cp.async.wait_group 1;" ::: "memory");
        }
        __syncthreads();

        const uint32_t sb = (uint32_t)(kc & 1) * STG_BYTES;
#pragma unroll
        for (int h = 0; h < 2; h++) {
            const uint32_t hoff = sb + h * 32;
            uint32_t ah[2][4], al[2][4];
            ldm_x4(ah[0], aHiB + hoff);
            ldm_x4(ah[1], aHiB + hoff + 16 * ROW_B);
            ldm_x4(al[0], aLoB + hoff);
            ldm_x4(al[1], aLoB + hoff + 16 * ROW_B);
#pragma unroll
            for (int p = 0; p < 4; p++) {
                uint32_t bh[4], bl[4];
                ldm_x4(bh, bHiB + hoff + p * (16 * ROW_B));
                ldm_x4(bl, bLoB + hoff + p * (16 * ROW_B));
#pragma unroll
                for (int t = 0; t < 2; t++) {
                    // interleave across two accumulator quads (dep distance 2)
                    mma_bf16(acc[t][2 * p],     ah[t], bh[0], bh[1]);
                    mma_bf16(acc[t][2 * p + 1], ah[t], bh[2], bh[3]);
                    mma_bf16(acc[t][2 * p],     ah[t], bl[0], bl[1]);
                    mma_bf16(acc[t][2 * p + 1], ah[t], bl[2], bl[3]);
                    mma_bf16(acc[t][2 * p],     al[t], bh[0], bh[1]);
                    mma_bf16(acc[t][2 * p + 1], al[t], bh[2], bh[3]);
                }
            }
        }
        __syncthreads();
        if (kc + 2 < 16) load_stage(kc & 1, kc + 2);
    }

    // -------- epilogue: stage accumulators in smem as f32 [128][132] --------
    float* sout = (float*)smem;
#pragma unroll
    for (int t = 0; t < 2; t++)
#pragma unroll
        for (int j = 0; j < 8; j++) {
            const int row = wm * 32 + t * 16 + (lane >> 2);
            const int col = wn * 64 + j * 8 + (lane & 3) * 2;
            sout[row * 132 + col]           = acc[t][j][0];
            sout[row * 132 + col + 1]       = acc[t][j][1];
            sout[(row + 8) * 132 + col]     = acc[t][j][2];
            sout[(row + 8) * 132 + col + 1] = acc[t][j][3];
        }
    __syncthreads();

#pragma unroll
    for (int i = 0; i < 16; i++) {
        const int lin = tid + i * 256;   // 0..4095
        const int row = lin >> 5;
        const int q = lin & 31;
        const int gr = m0 + row;
        if (gr >= M) continue;
        float4 v = *(float4*)&sout[row * 132 + q * 4];
        const float4 bb = __ldg((const float4*)&bias[n0 + q * 4]);
        v.x = fmaxf(v.x + bb.x, 0.0f);
        v.y = fmaxf(v.y + bb.y, 0.0f);
        v.z = fmaxf(v.z + bb.z, 0.0f);
        v.w = fmaxf(v.w + bb.w, 0.0f);
        if (OUT_MODE == 0) {
            __nv_bfloat16 h0 = __float2bfloat16(v.x);
            __nv_bfloat16 h1 = __float2bfloat16(v.y);
            __nv_bfloat16 h2 = __float2bfloat16(v.z);
            __nv_bfloat16 h3 = __float2bfloat16(v.w);
            uint2 vh, vl;
            vh.x = (uint32_t)__bfloat16_as_ushort(h0) |
                   ((uint32_t)__bfloat16_as_ushort(h1) << 16);
            vh.y = (uint32_t)__bfloat16_as_ushort(h2) |
                   ((uint32_t)__bfloat16_as_ushort(h3) << 16);
            vl.x = pack_bf16(v.x - __bfloat162float(h0),
                             v.y - __bfloat162float(h1));
            vl.y = pack_bf16(v.z - __bfloat162float(h2),
                             v.w - __bfloat162float(h3));
            const size_t off = (size_t)gr * N_TOTAL + n0 + q * 4;
            *(uint2*)((__nv_bfloat16*)outHiV + off) = vh;
            *(uint2*)((__nv_bfloat16*)outLoV + off) = vl;
        } else {
            *(float4*)((float*)outHiV + (size_t)gr * N_TOTAL + n0 + q * 4) = v;
        }
    }
}

// ===================== final tiny GEMM =====================
__global__ void gemm4_kernel(const float* __restrict__ A, const float* __restrict__ W4,
                             const float* __restrict__ b4, float* __restrict__ out12) {
    __shared__ float Ws[12][256];
    __shared__ float bs[12];
    int tid = threadIdx.x;  // 128
    for (int i = tid; i < 256 * 12; i += 128) {
        int k = i / 12, j = i % 12;
        Ws[j][k] = W4[i];
    }
    if (tid < 12) bs[tid] = b4[tid];
    __syncthreads();

    int warp = tid >> 5, lane = tid & 31;
    int row = blockIdx.x * 4 + warp;
    if (row >= N_FACES) return;
    const float* a = A + (size_t)row * 256;
    float acc[12];
#pragma unroll
    for (int j = 0; j < 12; j++) acc[j] = 0.0f;
    for (int k = lane; k < 256; k += 32) {
        float h = a[k];
#pragma unroll
        for (int j = 0; j < 12; j++) acc[j] += h * Ws[j][k];
    }
#pragma unroll
    for (int j = 0; j < 12; j++) {
#pragma unroll
        for (int off = 16; off; off >>= 1)
            acc[j] += __shfl_down_sync(0xffffffffu, acc[j], off);
    }
    if (lane == 0) {
#pragma unroll
        for (int j = 0; j < 12; j++) out12[(size_t)row * 12 + j] = acc[j] + bs[j];
    }
}

// ===================== procrustes + transform + scatter =====================
__device__ __forceinline__ void jrot(double A[3][3], double V[3][3], int p, int q) {
    double apq = A[p][q];
    if (fabs(apq) < 1e-300) return;
    double tau = (A[q][q] - A[p][p]) / (2.0 * apq);
    double t = copysign(1.0, tau) / (fabs(tau) + sqrt(1.0 + tau * tau));
    double c = 1.0 / sqrt(1.0 + t * t);
    double s = t * c;
#pragma unroll
    for (int k = 0; k < 3; k++) {
        double akp = A[k][p], akq = A[k][q];
        A[k][p] = c * akp - s * akq;
        A[k][q] = s * akp + c * akq;
    }
#pragma unroll
    for (int k = 0; k < 3; k++) {
        double apk = A[p][k], aqk = A[q][k];
        A[p][k] = c * apk - s * aqk;
        A[q][k] = s * apk + c * aqk;
    }
#pragma unroll
    for (int k = 0; k < 3; k++) {
        double vkp = V[k][p], vkq = V[k][q];
        V[k][p] = c * vkp - s * vkq;
        V[k][q] = s * vkp + c * vkq;
    }
}

__global__ void procrustes_kernel(const float* __restrict__ out12,
                                  const float* __restrict__ verts,
                                  const int* __restrict__ faces,
                                  float* __restrict__ out_trans,
                                  float* __restrict__ out_rot) {
    int f = blockIdx.x * blockDim.x + threadIdx.x;
    if (f >= N_FACES) return;

    double Mm[3][3];
#pragma unroll
    for (int i = 0; i < 3; i++)
#pragma unroll
        for (int j = 0; j < 3; j++)
            Mm[i][j] = (double)out12[(size_t)f * 12 + i * 3 + j];

    double A[3][3], V[3][3];
#pragma unroll
    for (int i = 0; i < 3; i++)
#pragma unroll
        for (int j = 0; j < 3; j++) {
            double s = 0.0;
#pragma unroll
            for (int k = 0; k < 3; k++) s += Mm[k][i] * Mm[k][j];
            A[i][j] = s;
            V[i][j] = (i == j) ? 1.0 : 0.0;
        }

#pragma unroll
    for (int sweep = 0; sweep < 8; sweep++) {
        jrot(A, V, 0, 1);
        jrot(A, V, 0, 2);
        jrot(A, V, 1, 2);
    }

    double lam[3] = {A[0][0], A[1][1], A[2][2]};
#pragma unroll
    for (int a = 0; a < 2; a++) {
        int mx = a;
#pragma unroll
        for (int b = 0; b < 3; b++)
            if (b > a && lam[b] > lam[mx]) mx = b;
        if (mx != a) {
            double tl = lam[a]; lam[a] = lam[mx]; lam[mx] = tl;
#pragma unroll
            for (int k = 0; k < 3; k++) {
                double tv = V[k][a]; V[k][a] = V[k][mx]; V[k][mx] = tv;
            }
        }
    }

    double Bc[3][3];
#pragma unroll
    for (int i = 0; i < 3; i++)
#pragma unroll
        for (int k = 0; k < 3; k++) {
            double s = 0.0;
#pragma unroll
            for (int j = 0; j < 3; j++) s += Mm[i][j] * V[j][k];
            Bc[i][k] = s;
        }

    double u1[3], u2[3], u3[3];
    double n1 = sqrt(Bc[0][0] * Bc[0][0] + Bc[1][0] * Bc[1][0] + Bc[2][0] * Bc[2][0]);
    double in1 = 1.0 / fmax(n1, 1e-150);
#pragma unroll
    for (int i = 0; i < 3; i++) u1[i] = Bc[i][0] * in1;
    double d12 = u1[0] * Bc[0][1] + u1[1] * Bc[1][1] + u1[2] * Bc[2][1];
    double w[3];
#pragma unroll
    for (int i = 0; i < 3; i++) w[i] = Bc[i][1] - d12 * u1[i];
    double n2 = sqrt(w[0] * w[0] + w[1] * w[1] + w[2] * w[2]);
    double in2 = 1.0 / fmax(n2, 1e-150);
#pragma unroll
    for (int i = 0; i < 3; i++) u2[i] = w[i] * in2;
    u3[0] = u1[1] * u2[2] - u1[2] * u2[1];
    u3[1] = u1[2] * u2[0] - u1[0] * u2[2];
    u3[2] = u1[0] * u2[1] - u1[1] * u2[0];

    double detV = V[0][0] * (V[1][1] * V[2][2] - V[1][2] * V[2][1])
                - V[0][1] * (V[1][0] * V[2][2] - V[1][2] * V[2][0])
                + V[0][2] * (V[1][0] * V[2][1] - V[1][1] * V[2][0]);

    float R[3][3];
#pragma unroll
    for (int i = 0; i < 3; i++)
#pragma unroll
        for (int j = 0; j < 3; j++)
            R[i][j] = (float)(u1[i] * V[j][0] + u2[i] * V[j][1] + detV * u3[i] * V[j][2]);

#pragma unroll
    for (int i = 0; i < 3; i++)
#pragma unroll
        for (int j = 0; j < 3; j++)
            out_rot[(size_t)f * 9 + i * 3 + j] = R[i][j];

    float t0 = out12[(size_t)f * 12 + 9];
    float t1 = out12[(size_t)f * 12 + 10];
    float t2 = out12[(size_t)f * 12 + 11];

#pragma unroll
    for (int c = 0; c < 3; c++) {
        int vi = faces[f * 3 + c];
        float vx = verts[(size_t)vi * 3 + 0];
        float vy = verts[(size_t)vi * 3 + 1];
        float vz = verts[(size_t)vi * 3 + 2];
        float tvx = vx * R[0][0] + vy * R[1][0] + vz * R[2][0] + t0;
        float tvy = vx * R[0][1] + vy * R[1][1] + vz * R[2][1] + t1;
        float tvz = vx * R[0][2] + vy * R[1][2] + vz * R[2][2] + t2;
        out_trans[(size_t)f * 9 + c * 3 + 0] = tvx;
        out_trans[(size_t)f * 9 + c * 3 + 1] = tvy;
        out_trans[(size_t)f * 9 + c * 3 + 2] = tvz;
        atomicAdd(&g_sum[vi * 3 + 0], tvx);
        atomicAdd(&g_sum[vi * 3 + 1], tvy);
        atomicAdd(&g_sum[vi * 3 + 2], tvz);
        atomicAdd(&g_cnt[vi], 1.0f);
    }
}

// ===================== finalize segment mean =====================
__global__ void finalize_kernel(float* __restrict__ out_vfeat) {
    int v = blockIdx.x * blockDim.x + threadIdx.x;
    if (v >= N_VERTS) return;
    float c = fmaxf(g_cnt[v], 1.0f);
    float inv = 1.0f / c;
    out_vfeat[v * 3 + 0] = g_sum[v * 3 + 0] * inv;
    out_vfeat[v * 3 + 1] = g_sum[v * 3 + 1] * inv;
    out_vfeat[v * 3 + 2] = g_sum[v * 3 + 2] * inv;
}

// ===================== launch =====================
extern "C" void kernel_launch(void* const* d_in, const int* in_sizes, int n_in,
                              void* d_out, int out_size) {
    const float* verts    = (const float*)d_in[0];
    const float* features = (const float*)d_in[1];
    const int*   faces    = (const int*)d_in[2];
    const float* W1 = (const float*)d_in[3];
    const float* b1 = (const float*)d_in[4];
    const float* W2 = (const float*)d_in[5];
    const float* b2 = (const float*)d_in[6];
    const float* W3 = (const float*)d_in[7];
    const float* b3 = (const float*)d_in[8];
    const float* W4 = (const float*)d_in[9];
    const float* b4 = (const float*)d_in[10];

    float* out = (float*)d_out;
    float* out_vfeat = out;
    float* out_trans = out + (size_t)N_VERTS * 3;
    float* out_rot   = out_trans + (size_t)N_FACES * 9;

    __nv_bfloat16 *p_x_hi, *p_x_lo, *p_y_hi, *p_y_lo;
    __nv_bfloat16 *p_w1h, *p_w1l, *p_w2h, *p_w2l, *p_w3h, *p_w3l;
    float *p_h3, *p_out12;
    cudaGetSymbolAddress((void**)&p_x_hi, g_x_hi);
    cudaGetSymbolAddress((void**)&p_x_lo, g_x_lo);
    cudaGetSymbolAddress((void**)&p_y_hi, g_y_hi);
    cudaGetSymbolAddress((void**)&p_y_lo, g_y_lo);
    cudaGetSymbolAddress((void**)&p_w1h, g_w1t_hi);
    cudaGetSymbolAddress((void**)&p_w1l, g_w1t_lo);
    cudaGetSymbolAddress((void**)&p_w2h, g_w2t_hi);
    cudaGetSymbolAddress((void**)&p_w2l, g_w2t_lo);
    cudaGetSymbolAddress((void**)&p_w3h, g_w3t_hi);
    cudaGetSymbolAddress((void**)&p_w3l, g_w3t_lo);
    cudaGetSymbolAddress((void**)&p_h3, g_h3);
    cudaGetSymbolAddress((void**)&p_out12, g_out12);

    cudaFuncSetAttribute(gemm_hmma<512, 0>,
                         cudaFuncAttributeMaxDynamicSharedMemorySize, SM_TOTAL_G);
    cudaFuncSetAttribute(gemm_hmma<256, 1>,
                         cudaFuncAttributeMaxDynamicSharedMemorySize, SM_TOTAL_G);

    // 1. zero accumulators
    zero_kernel<<<(N_VERTS * 3 + 255) / 256, 256>>>();

    // 2. weight transpose + split
    convert_w_kernel<<<(DIM * DIM + 255) / 256, 256>>>(W1, p_w1h, p_w1l, DIM, DIM);
    convert_w_kernel<<<(DIM * DIM + 255) / 256, 256>>>(W2, p_w2h, p_w2l, DIM, DIM);
    convert_w_kernel<<<(DIM * 256 + 255) / 256, 256>>>(W3, p_w3h, p_w3l, DIM, 256);

    // 3. gather + mean -> bf16 split
    gather_mean_kernel<<<N_FACES, 128>>>(features, faces, p_x_hi, p_x_lo);

    // 4. MLP on HMMA tensor cores
    {
        dim3 blk(256);
        dim3 g12(4, (N_FACES + 127) / 128);
        gemm_hmma<512, 0><<<g12, blk, SM_TOTAL_G>>>(p_x_hi, p_x_lo, p_w1h, p_w1l,
                                                    b1, p_y_hi, p_y_lo, N_FACES);
        gemm_hmma<512, 0><<<g12, blk, SM_TOTAL_G>>>(p_y_hi, p_y_lo, p_w2h, p_w2l,
                                                    b2, p_x_hi, p_x_lo, N_FACES);
        dim3 g3(2, (N_FACES + 127) / 128);
        gemm_hmma<256, 1><<<g3, blk, SM_TOTAL_G>>>(p_x_hi, p_x_lo, p_w3h, p_w3l,
                                                   b3, p_h3, nullptr, N_FACES);
        gemm4_kernel<<<(N_FACES + 3) / 4, 128>>>(p_h3, W4, b4, p_out12);
    }

    // 5. procrustes + transform + scatter
    procrustes_kernel<<<(N_FACES + 255) / 256, 256>>>(p_out12, verts, faces,
                                                      out_trans, out_rot);

    // 6. segment mean
    finalize_kernel<<<(N_VERTS + 255) / 256, 256>>>(out_vfeat);
}